// round 15
// baseline (speedup 1.0000x reference)
#include <cuda_runtime.h>
#include <math.h>

#define N_NODES 50000
#define N_EDGES 1600000
#define KKEEP   30000
#define NPAD    50176          // 49 * 1024 == 196*256 (k_init grid covers it exactly)
#define NBLK_SORT 49
#define HISTN   (256*NBLK_SORT)
#define SCAN_TILE 4096

// ---------------- static device scratch (no allocation allowed) -------------
__device__ float g_h0[N_NODES*4];
__device__ float g_h1[N_NODES*32];
__device__ float g_h2[N_NODES*64];
__device__ float g_h3[N_NODES*128];
__device__ float g_agg[N_NODES*128];
__device__ float g_hk[KKEEP*128];
__device__ float g_score[N_NODES];

__device__ int g_off[N_NODES+1];
__device__ int g_cur[N_NODES];
__device__ int g_csr[N_EDGES];
__device__ int g_off2[KKEEP+1];
__device__ int g_cur2[KKEEP];
__device__ int g_csr2[N_EDGES];

__device__ unsigned g_keysA[NPAD], g_keysB[NPAD];
__device__ int      g_valsA[NPAD], g_valsB[NPAD];
__device__ int      g_hist[HISTN], g_offs[HISTN];
__device__ int      g_newid[N_NODES];
__device__ float    g_gsum[512];
__device__ int      g_bsum[64];

__device__ __forceinline__ float gelu_f(float v){
    return 0.5f*v*(1.0f + erff(v*0.70710678118654752440f));
}

// ---------------- init: zero counters, newid=-1, pad sort keys ---------------
__global__ void k_init(){
    int i = blockIdx.x*blockDim.x + threadIdx.x;
    if (i < N_NODES){ g_cur[i] = 0; g_newid[i] = -1; }
    else if (i < NPAD){ g_keysA[i] = 0xFFFFFFFFu; g_valsA[i] = -1; }
    if (i < KKEEP)  g_cur2[i] = 0;
    if (i < 512)    g_gsum[i] = 0.f;
}

// ---------------- dense input layer: h0 = gelu(x @ wd_root + b) -------------
__global__ void k_dense(const float* __restrict__ x,
                        const float* __restrict__ w,
                        const float* __restrict__ b){
    __shared__ float ws[256];
    __shared__ float bs[4];
    int t = threadIdx.x;
    if (t < 256) ws[t] = w[t];
    if (t < 4)   bs[t] = b[t];
    __syncthreads();
    int i = blockIdx.x*256 + t;
    if (i >= N_NODES) return;
    float a0=bs[0], a1=bs[1], a2=bs[2], a3=bs[3];
    const float4* x4 = (const float4*)(x + (size_t)i*64);
    #pragma unroll
    for (int q=0;q<16;q++){
        float4 xv = x4[q];
        const float* wp = ws + q*16;
        a0 += xv.x*wp[0] + xv.y*wp[4] + xv.z*wp[8]  + xv.w*wp[12];
        a1 += xv.x*wp[1] + xv.y*wp[5] + xv.z*wp[9]  + xv.w*wp[13];
        a2 += xv.x*wp[2] + xv.y*wp[6] + xv.z*wp[10] + xv.w*wp[14];
        a3 += xv.x*wp[3] + xv.y*wp[7] + xv.z*wp[11] + xv.w*wp[15];
    }
    ((float4*)g_h0)[i] = make_float4(gelu_f(a0),gelu_f(a1),gelu_f(a2),gelu_f(a3));
}

// ---------------- CSR build --------------------------------------------------
__global__ void k_deg(const int* __restrict__ ei){
    int e = blockIdx.x*blockDim.x + threadIdx.x;
    if (e < N_EDGES) atomicAdd(&g_cur[ei[N_EDGES + e]], 1);
}
__global__ void k_scatter(const int* __restrict__ ei){
    int e = blockIdx.x*blockDim.x + threadIdx.x;
    if (e < N_EDGES){
        int d = ei[N_EDGES + e];
        int p = atomicAdd(&g_cur[d], 1);
        g_csr[p] = ei[e];
    }
}

// ---------------- multi-block exclusive scan (3 phases) ----------------------
__device__ __forceinline__ void scan_src(int mode, const int*& in, int& n){
    if (mode==0){ in=g_cur;  n=N_NODES; }
    else if (mode==1){ in=g_cur2; n=KKEEP; }
    else { in=g_hist; n=HISTN; }
}

__global__ void k_scanA(int mode){
    const int* in; int n;
    scan_src(mode, in, n);
    int t = threadIdx.x;
    int base = blockIdx.x*SCAN_TILE + t*16;
    int s = 0;
    #pragma unroll
    for (int j=0;j<16;j++){ int i = base+j; if (i < n) s += in[i]; }
    __shared__ int red[256];
    red[t] = s;
    __syncthreads();
    #pragma unroll
    for (int st=128; st; st>>=1){
        if (t < st) red[t] += red[t+st];
        __syncthreads();
    }
    if (t == 0) g_bsum[blockIdx.x] = red[0];
}

__global__ void k_scanB(int mode){
    int n = (mode==0)?N_NODES:(mode==1)?KKEEP:HISTN;
    int nb = (n + SCAN_TILE - 1)/SCAN_TILE;
    int t = threadIdx.x;
    int v = (t < nb) ? g_bsum[t] : 0;
    int incl = v;
    #pragma unroll
    for (int o=1;o<32;o<<=1){
        int u = __shfl_up_sync(0xffffffffu, incl, o);
        if (t >= o) incl += u;
    }
    if (t < nb) g_bsum[t] = incl - v;
    if (t == nb-1){
        if (mode==0) g_off[N_NODES] = incl;
        else if (mode==1) g_off2[KKEEP] = incl;
    }
}

__global__ void k_scanC(int mode){
    const int* in; int* out; int* cpy; int n;
    if (mode==0){ in=g_cur;  out=g_off;  cpy=g_cur;  n=N_NODES; }
    else if (mode==1){ in=g_cur2; out=g_off2; cpy=g_cur2; n=KKEEP; }
    else { in=g_hist; out=g_offs; cpy=0; n=HISTN; }
    int t = threadIdx.x;
    int base = blockIdx.x*SCAN_TILE + t*16;
    int vals[16]; int s = 0;
    #pragma unroll
    for (int j=0;j<16;j++){
        int i = base+j;
        vals[j] = (i < n) ? in[i] : 0;
        s += vals[j];
    }
    __shared__ int sh[256];
    sh[t] = s;
    __syncthreads();
    #pragma unroll
    for (int d=1; d<256; d<<=1){
        int v = 0;
        if (t >= d) v = sh[t-d];
        __syncthreads();
        if (t >= d) sh[t] += v;
        __syncthreads();
    }
    int run = g_bsum[blockIdx.x] + sh[t] - s;
    #pragma unroll
    for (int j=0;j<16;j++){
        int i = base+j;
        if (i < n){
            out[i] = run;
            if (cpy) cpy[i] = run;
            run += vals[j];
        }
    }
}

// ---------------- aggregation, F=4 -------------------------------------------
__global__ void k_agg4(){
    int gw = (blockIdx.x*blockDim.x + threadIdx.x) >> 5;
    int lane = threadIdx.x & 31;
    if (gw >= N_NODES) return;
    int s0 = g_off[gw], s1 = g_off[gw+1];
    float4 acc = make_float4(0,0,0,0);
    for (int e = s0 + lane; e < s1; e += 32){
        int s = g_csr[e];
        float4 v = *(const float4*)(g_h0 + (size_t)s*4);
        acc.x += v.x; acc.y += v.y; acc.z += v.z; acc.w += v.w;
    }
    #pragma unroll
    for (int o=16;o;o>>=1){
        acc.x += __shfl_down_sync(0xffffffffu, acc.x, o);
        acc.y += __shfl_down_sync(0xffffffffu, acc.y, o);
        acc.z += __shfl_down_sync(0xffffffffu, acc.z, o);
        acc.w += __shfl_down_sync(0xffffffffu, acc.w, o);
    }
    if (lane == 0) *(float4*)(g_agg + (size_t)gw*4) = acc;
}

// ---------------- aggregation, F in {32,64,128} (warp per node) --------------
template<int LAYER>
__global__ void k_agg(){
    constexpr int F = (LAYER==1)?32:(LAYER==2)?64:128;
    constexpr int V = F/32;
    const float* __restrict__ hin = (LAYER==1)?g_h1:(LAYER==2)?g_h2:g_hk;
    const int* __restrict__ off   = (LAYER==3)?g_off2:g_off;
    const int* __restrict__ csr   = (LAYER==3)?g_csr2:g_csr;
    const int n = (LAYER==3)?KKEEP:N_NODES;

    int gw = (blockIdx.x*blockDim.x + threadIdx.x) >> 5;
    int lane = threadIdx.x & 31;
    if (gw >= n) return;
    float acc[V];
    #pragma unroll
    for (int v=0;v<V;v++) acc[v]=0.f;
    int s1 = off[gw+1];
    for (int base = off[gw]; base < s1; base += 32){
        int idx = base + lane;
        int s = (idx < s1) ? csr[idx] : 0;
        int cnt = s1 - base; if (cnt > 32) cnt = 32;
        for (int j=0;j<cnt;j++){
            int sj = __shfl_sync(0xffffffffu, s, j);
            const float* hp = hin + (size_t)sj*F + lane;
            #pragma unroll
            for (int v=0;v<V;v++) acc[v] += hp[v*32];
        }
    }
    float* ap = g_agg + (size_t)gw*F + lane;
    #pragma unroll
    for (int v=0;v<V;v++) ap[v*32] = acc[v];
}

// ---------------- conv0: Fin=4 -> 32 -----------------------------------------
__global__ void k_conv0(const float* __restrict__ wrel,
                        const float* __restrict__ wroot,
                        const float* __restrict__ b){
    __shared__ float wr[128], wt[128], bs[32];
    int t = threadIdx.x;
    if (t < 128){ wr[t] = wrel[t]; wt[t] = wroot[t]; }
    if (t < 32) bs[t] = b[t];
    __syncthreads();
    int i = blockIdx.x*256 + t;
    if (i >= N_NODES) return;
    float4 av = ((const float4*)g_agg)[i];
    float4 hv = ((const float4*)g_h0)[i];
    float a[4] = {av.x,av.y,av.z,av.w};
    float h[4] = {hv.x,hv.y,hv.z,hv.w};
    #pragma unroll
    for (int c=0;c<32;c++){
        float acc = bs[c];
        #pragma unroll
        for (int k=0;k<4;k++) acc += a[k]*wr[k*32+c] + h[k]*wt[k*32+c];
        g_h1[(size_t)i*32 + c] = gelu_f(acc);
    }
}

// ---------------- fast tiled GEMM + bias + gelu (+ fused parity pool on L3) --
// out = gelu( [agg , h] @ [Wrel ; Wroot] + b )
// BM=128, BN = 64 (L1) / 128 (L2,L3). 256 threads, micro-tile 8 x (BN/16).
template<int LAYER>
__global__ void __launch_bounds__(256) k_gemm(const float* __restrict__ Wrel,
                       const float* __restrict__ Wroot,
                       const float* __restrict__ bias){
    constexpr int FIN  = (LAYER==1)?32:(LAYER==2)?64:128;
    constexpr int NOUT = 2*FIN;
    constexpr int KK   = 2*FIN;
    constexpr int BM   = 128;
    constexpr int BN   = (LAYER==1)?64:128;
    constexpr int BK   = 16;
    constexpr int TM   = 8;
    constexpr int TN   = BN/16;         // 4 or 8
    const float* __restrict__ Aagg = g_agg;
    const float* __restrict__ Ah   = (LAYER==1)?g_h1:(LAYER==2)?g_h2:g_hk;
    float* __restrict__ Out        = (LAYER==1)?g_h2:(LAYER==2)?g_h3:0;
    const int M = (LAYER==3)?KKEEP:N_NODES;

    __shared__ __align__(16) float As[BK][BM];     // transposed A tile
    __shared__ __align__(16) float Bs[BK][BN];

    const int bm = blockIdx.x*BM, bn = blockIdx.y*BN;
    const int tid = threadIdx.x;
    const int tx = tid & 15, ty = tid >> 4;

    // A-loader indices: 4 float4 per 16-wide row slice
    const int aRow = tid >> 2;          // 0..63
    const int aCol = (tid & 3) * 4;     // 0,4,8,12
    // B-loader indices
    const int bRow = (BN==128) ? (tid >> 5) : (tid >> 4);   // k within tile
    const int bCol = ((BN==128) ? (tid & 31) : (tid & 15)) * 4;

    float acc[TM][TN];
    #pragma unroll
    for (int i=0;i<TM;i++)
        #pragma unroll
        for (int j=0;j<TN;j++) acc[i][j]=0.f;

    for (int k0=0;k0<KK;k0+=BK){
        // load A (transposed into As[kk][r]); float4 never straddles agg/h
        #pragma unroll
        for (int rr=0; rr<BM; rr+=64){
            int row = bm + aRow + rr;
            int k = k0 + aCol;
            float4 v = make_float4(0,0,0,0);
            if (row < M){
                const float* src = (k < FIN) ? (Aagg + (size_t)row*FIN + k)
                                             : (Ah   + (size_t)row*FIN + (k-FIN));
                v = *(const float4*)src;
            }
            As[aCol+0][aRow+rr] = v.x;
            As[aCol+1][aRow+rr] = v.y;
            As[aCol+2][aRow+rr] = v.z;
            As[aCol+3][aRow+rr] = v.w;
        }
        // load B
        #pragma unroll
        for (int kk2=0; kk2<BK; kk2 += (BN==128?8:16)){
            int k = k0 + bRow + kk2;
            const float* src = (k < FIN) ? (Wrel  + (size_t)k*NOUT + bn + bCol)
                                         : (Wroot + (size_t)(k-FIN)*NOUT + bn + bCol);
            *(float4*)&Bs[bRow+kk2][bCol] = *(const float4*)src;
        }
        __syncthreads();
        #pragma unroll
        for (int kk=0;kk<BK;kk++){
            float a[TM], b[TN];
            *(float4*)&a[0] = *(const float4*)&As[kk][ty*TM];
            *(float4*)&a[4] = *(const float4*)&As[kk][ty*TM+4];
            #pragma unroll
            for (int j=0;j<TN;j+=4)
                *(float4*)&b[j] = *(const float4*)&Bs[kk][tx*TN+j];
            #pragma unroll
            for (int i=0;i<TM;i++)
                #pragma unroll
                for (int j=0;j<TN;j++) acc[i][j] += a[i]*b[j];
        }
        __syncthreads();
    }

    if (LAYER != 3){
        float bv[TN];
        #pragma unroll
        for (int j=0;j<TN;j++) bv[j] = bias[bn + tx*TN + j];
        #pragma unroll
        for (int i=0;i<TM;i++){
            int row = bm + ty*TM + i;
            if (row < M){
                float o[TN];
                #pragma unroll
                for (int j=0;j<TN;j++) o[j] = gelu_f(acc[i][j] + bv[j]);
                #pragma unroll
                for (int j=0;j<TN;j+=4)
                    *(float4*)(Out + (size_t)row*NOUT + bn + tx*TN + j) = *(float4*)&o[j];
            }
        }
    } else {
        // fused parity mean-pool: sum gelu(acc+bias) by global-row parity
        float bv[TN];
        #pragma unroll
        for (int j=0;j<TN;j++) bv[j] = bias[bn + tx*TN + j];
        float p0[TN], p1[TN];
        #pragma unroll
        for (int j=0;j<TN;j++){ p0[j]=0.f; p1[j]=0.f; }
        #pragma unroll
        for (int i=0;i<TM;i++){
            int row = bm + ty*TM + i;          // parity == i&1 (bm, ty*TM even)
            if (row < M){
                #pragma unroll
                for (int j=0;j<TN;j++){
                    float g = gelu_f(acc[i][j] + bv[j]);
                    if (i & 1) p1[j] += g; else p0[j] += g;
                }
            }
        }
        __shared__ float psum[2][16][BN];      // [parity][ty][col]
        #pragma unroll
        for (int j=0;j<TN;j++){
            psum[0][ty][tx*TN+j] = p0[j];
            psum[1][ty][tx*TN+j] = p1[j];
        }
        __syncthreads();
        // 256 threads reduce 2*BN columns over 16 ty groups
        int p = tid >> 7, col = tid & 127;     // BN==128 here
        float s = 0.f;
        #pragma unroll
        for (int g=0; g<16; g++) s += psum[p][g][col];
        atomicAdd(&g_gsum[p*256 + bn + col], s);
    }
}

// ---------------- score + sort keys, warp per node ----------------------------
__global__ void k_score(const float* __restrict__ p){
    int gw = (blockIdx.x*blockDim.x + threadIdx.x) >> 5;
    int lane = threadIdx.x & 31;
    if (gw >= N_NODES) return;
    float4 pv = ((const float4*)p)[lane];
    float4 hv = ((const float4*)(g_h3 + (size_t)gw*128))[lane];
    float dot = hv.x*pv.x + hv.y*pv.y + hv.z*pv.z + hv.w*pv.w;
    float pp  = pv.x*pv.x + pv.y*pv.y + pv.z*pv.z + pv.w*pv.w;
    #pragma unroll
    for (int o=16;o;o>>=1){
        dot += __shfl_xor_sync(0xffffffffu, dot, o);
        pp  += __shfl_xor_sync(0xffffffffu, pp,  o);
    }
    if (lane == 0){
        float s = tanhf(dot / sqrtf(pp));
        g_score[gw] = s;
        unsigned u = __float_as_uint(s);
        unsigned asc = (u & 0x80000000u) ? ~u : (u | 0x80000000u);
        g_keysA[gw] = ~asc;              // ascending key = descending score
        g_valsA[gw] = gw;
    }
}

// ---------------- stable radix sort ------------------------------------------
__global__ void k_sorthist(int pass){
    __shared__ int sh[256];
    int t = threadIdx.x;
    if (t < 256) sh[t] = 0;
    __syncthreads();
    int gid = blockIdx.x*1024 + t;
    unsigned key = (pass & 1) ? g_keysB[gid] : g_keysA[gid];
    int d = (key >> (pass*8)) & 255;
    atomicAdd(&sh[d], 1);
    __syncthreads();
    if (t < 256) g_hist[t*NBLK_SORT + blockIdx.x] = sh[t];
}

__global__ void k_sortscatter(int pass){
    __shared__ int wc[32*256];
    int t = threadIdx.x;
    int w = t >> 5, lane = t & 31;
    for (int i=t;i<32*256;i+=1024) wc[i] = 0;
    __syncthreads();
    int gid = blockIdx.x*1024 + t;
    unsigned key; int val;
    if (pass & 1){ key = g_keysB[gid]; val = g_valsB[gid]; }
    else         { key = g_keysA[gid]; val = g_valsA[gid]; }
    int d = (key >> (pass*8)) & 255;
    unsigned m = __match_any_sync(0xffffffffu, d);
    int lr = __popc(m & ((1u << lane) - 1u));
    int leader = __ffs(m) - 1;
    if (lane == leader) wc[w*256 + d] = __popc(m);
    __syncthreads();
    if (t < 256){
        int run = 0;
        #pragma unroll
        for (int ww=0; ww<32; ww++){
            int tmp = wc[ww*256 + t];
            wc[ww*256 + t] = run;
            run += tmp;
        }
    }
    __syncthreads();
    int pos = g_offs[d*NBLK_SORT + blockIdx.x] + wc[w*256 + d] + lr;
    if (pass & 1){ g_keysA[pos] = key; g_valsA[pos] = val; }
    else         { g_keysB[pos] = key; g_valsB[pos] = val; }
}

// ---------------- gather kept nodes -------------------------------------------
__global__ void k_hk(){
    int r = (blockIdx.x*blockDim.x + threadIdx.x) >> 5;
    int lane = threadIdx.x & 31;
    if (r >= KKEEP) return;
    int orig = g_valsA[r];
    float v = g_score[orig];
    float4 hv = ((const float4*)(g_h3 + (size_t)orig*128))[lane];
    hv.x *= v; hv.y *= v; hv.z *= v; hv.w *= v;
    ((float4*)(g_hk + (size_t)r*128))[lane] = hv;
    if (lane == 0) g_newid[orig] = r;
}

// ---------------- filtered CSR over kept nodes -------------------------------
__global__ void k_deg2(const int* __restrict__ ei){
    int e = blockIdx.x*blockDim.x + threadIdx.x;
    if (e >= N_EDGES) return;
    int s2 = g_newid[ei[e]];
    int d2 = g_newid[ei[N_EDGES + e]];
    if (s2 >= 0 && d2 >= 0) atomicAdd(&g_cur2[d2], 1);
}
__global__ void k_scatter2(const int* __restrict__ ei){
    int e = blockIdx.x*blockDim.x + threadIdx.x;
    if (e >= N_EDGES) return;
    int s2 = g_newid[ei[e]];
    int d2 = g_newid[ei[N_EDGES + e]];
    if (s2 >= 0 && d2 >= 0){
        int p = atomicAdd(&g_cur2[d2], 1);
        g_csr2[p] = s2;
    }
}

// ---------------- final projection --------------------------------------------
__global__ void k_final(const float* __restrict__ w_out,
                        const float* __restrict__ b_out,
                        float* __restrict__ out){
    __shared__ float red[256];
    int t = threadIdx.x;
    const float inv = 1.0f/15000.0f;
    float acc = g_gsum[t]*inv*w_out[t] + g_gsum[256+t]*inv*w_out[256+t];
    red[t] = acc;
    __syncthreads();
    for (int s=128; s; s>>=1){
        if (t < s) red[t] += red[t+s];
        __syncthreads();
    }
    if (t == 0) out[0] = red[0] + b_out[0];
}

// ---------------- scan helper --------------------------------------------------
static inline void run_scan(int mode){
    int n = (mode==0)?N_NODES:(mode==1)?KKEEP:HISTN;
    int nb = (n + SCAN_TILE - 1)/SCAN_TILE;
    k_scanA<<<nb,256>>>(mode);
    k_scanB<<<1,32>>>(mode);
    k_scanC<<<nb,256>>>(mode);
}

// ---------------- launch sequence ----------------------------------------------
extern "C" void kernel_launch(void* const* d_in, const int* in_sizes, int n_in,
                              void* d_out, int out_size){
    const float* x       = (const float*)d_in[0];
    const int*   ei      = (const int*)  d_in[1];
    const float* wd_root = (const float*)d_in[2];
    const float* wd_b    = (const float*)d_in[3];
    const float* w0_rel  = (const float*)d_in[4];
    const float* w0_root = (const float*)d_in[5];
    const float* w0_b    = (const float*)d_in[6];
    const float* w1_rel  = (const float*)d_in[7];
    const float* w1_root = (const float*)d_in[8];
    const float* w1_b    = (const float*)d_in[9];
    const float* w2_rel  = (const float*)d_in[10];
    const float* w2_root = (const float*)d_in[11];
    const float* w2_b    = (const float*)d_in[12];
    const float* pool_p  = (const float*)d_in[13];
    const float* w3_rel  = (const float*)d_in[14];
    const float* w3_root = (const float*)d_in[15];
    const float* w3_b    = (const float*)d_in[16];
    const float* w_out   = (const float*)d_in[17];
    const float* b_out   = (const float*)d_in[18];
    float* out = (float*)d_out;

    const int GN256   = (N_NODES + 255)/256;          // 196 (== NPAD/256)
    const int GE256   = (N_EDGES + 255)/256;
    const int GWARP_N = (N_NODES*32 + 255)/256;
    const int GWARP_K = (KKEEP*32 + 255)/256;

    k_init<<<GN256,256>>>();
    k_dense<<<GN256,256>>>(x, wd_root, wd_b);

    // CSR (by dst), reused for convs 0-2
    k_deg<<<GE256,256>>>(ei);
    run_scan(0);
    k_scatter<<<GE256,256>>>(ei);

    // conv0: 4 -> 32
    k_agg4<<<GWARP_N,256>>>();
    k_conv0<<<GN256,256>>>(w0_rel, w0_root, w0_b);

    // conv1: 32 -> 64
    k_agg<1><<<GWARP_N,256>>>();
    k_gemm<1><<<dim3((N_NODES+127)/128, 1),256>>>(w1_rel, w1_root, w1_b);

    // conv2: 64 -> 128
    k_agg<2><<<GWARP_N,256>>>();
    k_gemm<2><<<dim3((N_NODES+127)/128, 1),256>>>(w2_rel, w2_root, w2_b);

    // topk: scores(+keys) + stable radix sort
    k_score<<<GWARP_N,256>>>(pool_p);
    for (int pass=0; pass<4; pass++){
        k_sorthist<<<NBLK_SORT,1024>>>(pass);
        run_scan(2);
        k_sortscatter<<<NBLK_SORT,1024>>>(pass);
    }
    k_hk<<<GWARP_K,256>>>();

    // filtered CSR + conv3: 128 -> 256 (pooling fused into epilogue)
    k_deg2<<<GE256,256>>>(ei);
    run_scan(1);
    k_scatter2<<<GE256,256>>>(ei);
    k_agg<3><<<GWARP_K,256>>>();
    k_gemm<3><<<dim3((KKEEP+127)/128, 2),256>>>(w3_rel, w3_root, w3_b);

    k_final<<<1,256>>>(w_out, b_out, out);
}

// round 16
// speedup vs baseline: 1.0110x; 1.0110x over previous
#include <cuda_runtime.h>
#include <math.h>

#define N_NODES 50000
#define N_EDGES 1600000
#define KKEEP   30000
#define NPAD    50176          // 49 * 1024 == 196*256 (k_init grid covers it exactly)
#define NBLK_SORT 49
#define HISTN   (256*NBLK_SORT)
#define SCAN_TILE 4096

// ---------------- static device scratch (no allocation allowed) -------------
__device__ __align__(128) float g_h0[N_NODES*4];
__device__ __align__(128) float g_h1[N_NODES*32];
__device__ __align__(128) float g_h2[N_NODES*64];
__device__ __align__(128) float g_h3[N_NODES*128];
__device__ __align__(128) float g_agg[N_NODES*128];
__device__ __align__(128) float g_hk[KKEEP*128];
__device__ float g_score[N_NODES];

__device__ int g_off[N_NODES+1];
__device__ int g_cur[N_NODES];
__device__ int g_csr[N_EDGES];
__device__ int g_off2[KKEEP+1];
__device__ int g_cur2[KKEEP];
__device__ int g_csr2[N_EDGES];

__device__ unsigned g_keysA[NPAD], g_keysB[NPAD];
__device__ int      g_valsA[NPAD], g_valsB[NPAD];
__device__ int      g_hist[HISTN], g_offs[HISTN];
__device__ int      g_newid[N_NODES];
__device__ float    g_gsum[512];
__device__ int      g_bsum[64];

__device__ __forceinline__ float gelu_f(float v){
    return 0.5f*v*(1.0f + erff(v*0.70710678118654752440f));
}

// ---------------- packed f32x2 helpers (Blackwell FFMA2) ---------------------
__device__ __forceinline__ unsigned long long pack2(float x, float y){
    unsigned long long r;
    asm("mov.b64 %0, {%1, %2};" : "=l"(r) : "f"(x), "f"(y));
    return r;
}
__device__ __forceinline__ unsigned long long fma2(unsigned long long a,
                                                   unsigned long long b,
                                                   unsigned long long c){
    unsigned long long d;
    asm("fma.rn.f32x2 %0, %1, %2, %3;" : "=l"(d) : "l"(a), "l"(b), "l"(c));
    return d;
}
__device__ __forceinline__ float2 unpack2(unsigned long long v){
    float lo, hi;
    asm("mov.b64 {%0, %1}, %2;" : "=f"(lo), "=f"(hi) : "l"(v));
    return make_float2(lo, hi);
}

// ---------------- init: zero counters, newid=-1, pad sort keys ---------------
__global__ void k_init(){
    int i = blockIdx.x*blockDim.x + threadIdx.x;
    if (i < N_NODES){ g_cur[i] = 0; g_newid[i] = -1; }
    else if (i < NPAD){ g_keysA[i] = 0xFFFFFFFFu; g_valsA[i] = -1; }
    if (i < KKEEP)  g_cur2[i] = 0;
    if (i < 512)    g_gsum[i] = 0.f;
}

// ---------------- dense input layer: h0 = gelu(x @ wd_root + b) -------------
__global__ void k_dense(const float* __restrict__ x,
                        const float* __restrict__ w,
                        const float* __restrict__ b){
    __shared__ float ws[256];
    __shared__ float bs[4];
    int t = threadIdx.x;
    if (t < 256) ws[t] = w[t];
    if (t < 4)   bs[t] = b[t];
    __syncthreads();
    int i = blockIdx.x*256 + t;
    if (i >= N_NODES) return;
    float a0=bs[0], a1=bs[1], a2=bs[2], a3=bs[3];
    const float4* x4 = (const float4*)(x + (size_t)i*64);
    #pragma unroll
    for (int q=0;q<16;q++){
        float4 xv = x4[q];
        const float* wp = ws + q*16;
        a0 += xv.x*wp[0] + xv.y*wp[4] + xv.z*wp[8]  + xv.w*wp[12];
        a1 += xv.x*wp[1] + xv.y*wp[5] + xv.z*wp[9]  + xv.w*wp[13];
        a2 += xv.x*wp[2] + xv.y*wp[6] + xv.z*wp[10] + xv.w*wp[14];
        a3 += xv.x*wp[3] + xv.y*wp[7] + xv.z*wp[11] + xv.w*wp[15];
    }
    ((float4*)g_h0)[i] = make_float4(gelu_f(a0),gelu_f(a1),gelu_f(a2),gelu_f(a3));
}

// ---------------- CSR build --------------------------------------------------
__global__ void k_deg(const int* __restrict__ ei){
    int e = blockIdx.x*blockDim.x + threadIdx.x;
    if (e < N_EDGES) atomicAdd(&g_cur[ei[N_EDGES + e]], 1);
}
__global__ void k_scatter(const int* __restrict__ ei){
    int e = blockIdx.x*blockDim.x + threadIdx.x;
    if (e < N_EDGES){
        int d = ei[N_EDGES + e];
        int p = atomicAdd(&g_cur[d], 1);
        g_csr[p] = ei[e];
    }
}

// ---------------- multi-block exclusive scan (3 phases) ----------------------
__device__ __forceinline__ void scan_src(int mode, const int*& in, int& n){
    if (mode==0){ in=g_cur;  n=N_NODES; }
    else if (mode==1){ in=g_cur2; n=KKEEP; }
    else { in=g_hist; n=HISTN; }
}

__global__ void k_scanA(int mode){
    const int* in; int n;
    scan_src(mode, in, n);
    int t = threadIdx.x;
    int base = blockIdx.x*SCAN_TILE + t*16;
    int s = 0;
    #pragma unroll
    for (int j=0;j<16;j++){ int i = base+j; if (i < n) s += in[i]; }
    __shared__ int red[256];
    red[t] = s;
    __syncthreads();
    #pragma unroll
    for (int st=128; st; st>>=1){
        if (t < st) red[t] += red[t+st];
        __syncthreads();
    }
    if (t == 0) g_bsum[blockIdx.x] = red[0];
}

__global__ void k_scanB(int mode){
    int n = (mode==0)?N_NODES:(mode==1)?KKEEP:HISTN;
    int nb = (n + SCAN_TILE - 1)/SCAN_TILE;
    int t = threadIdx.x;
    int v = (t < nb) ? g_bsum[t] : 0;
    int incl = v;
    #pragma unroll
    for (int o=1;o<32;o<<=1){
        int u = __shfl_up_sync(0xffffffffu, incl, o);
        if (t >= o) incl += u;
    }
    if (t < nb) g_bsum[t] = incl - v;
    if (t == nb-1){
        if (mode==0) g_off[N_NODES] = incl;
        else if (mode==1) g_off2[KKEEP] = incl;
    }
}

__global__ void k_scanC(int mode){
    const int* in; int* out; int* cpy; int n;
    if (mode==0){ in=g_cur;  out=g_off;  cpy=g_cur;  n=N_NODES; }
    else if (mode==1){ in=g_cur2; out=g_off2; cpy=g_cur2; n=KKEEP; }
    else { in=g_hist; out=g_offs; cpy=0; n=HISTN; }
    int t = threadIdx.x;
    int base = blockIdx.x*SCAN_TILE + t*16;
    int vals[16]; int s = 0;
    #pragma unroll
    for (int j=0;j<16;j++){
        int i = base+j;
        vals[j] = (i < n) ? in[i] : 0;
        s += vals[j];
    }
    __shared__ int sh[256];
    sh[t] = s;
    __syncthreads();
    #pragma unroll
    for (int d=1; d<256; d<<=1){
        int v = 0;
        if (t >= d) v = sh[t-d];
        __syncthreads();
        if (t >= d) sh[t] += v;
        __syncthreads();
    }
    int run = g_bsum[blockIdx.x] + sh[t] - s;
    #pragma unroll
    for (int j=0;j<16;j++){
        int i = base+j;
        if (i < n){
            out[i] = run;
            if (cpy) cpy[i] = run;
            run += vals[j];
        }
    }
}

// ---------------- aggregation, F=4 -------------------------------------------
__global__ void k_agg4(){
    int gw = (blockIdx.x*blockDim.x + threadIdx.x) >> 5;
    int lane = threadIdx.x & 31;
    if (gw >= N_NODES) return;
    int s0 = g_off[gw], s1 = g_off[gw+1];
    float4 acc = make_float4(0,0,0,0);
    for (int e = s0 + lane; e < s1; e += 32){
        int s = g_csr[e];
        float4 v = *(const float4*)(g_h0 + (size_t)s*4);
        acc.x += v.x; acc.y += v.y; acc.z += v.z; acc.w += v.w;
    }
    #pragma unroll
    for (int o=16;o;o>>=1){
        acc.x += __shfl_down_sync(0xffffffffu, acc.x, o);
        acc.y += __shfl_down_sync(0xffffffffu, acc.y, o);
        acc.z += __shfl_down_sync(0xffffffffu, acc.z, o);
        acc.w += __shfl_down_sync(0xffffffffu, acc.w, o);
    }
    if (lane == 0) *(float4*)(g_agg + (size_t)gw*4) = acc;
}

// ---------------- aggregation, F in {32,64,128} (warp per node) --------------
// lane owns V consecutive features -> one vector LDG per source row per lane
template<int LAYER>
__global__ void k_agg(){
    constexpr int F = (LAYER==1)?32:(LAYER==2)?64:128;
    constexpr int V = F/32;
    const float* __restrict__ hin = (LAYER==1)?g_h1:(LAYER==2)?g_h2:g_hk;
    const int* __restrict__ off   = (LAYER==3)?g_off2:g_off;
    const int* __restrict__ csr   = (LAYER==3)?g_csr2:g_csr;
    const int n = (LAYER==3)?KKEEP:N_NODES;

    int gw = (blockIdx.x*blockDim.x + threadIdx.x) >> 5;
    int lane = threadIdx.x & 31;
    if (gw >= n) return;
    float acc[V];
    #pragma unroll
    for (int v=0;v<V;v++) acc[v]=0.f;
    int s1 = off[gw+1];
    for (int base = off[gw]; base < s1; base += 32){
        int idx = base + lane;
        int s = (idx < s1) ? csr[idx] : 0;
        int cnt = s1 - base; if (cnt > 32) cnt = 32;
        for (int j=0;j<cnt;j++){
            int sj = __shfl_sync(0xffffffffu, s, j);
            const float* hp = hin + (size_t)sj*F + lane*V;
            if (V == 1){
                acc[0] += hp[0];
            } else if (V == 2){
                float2 v2 = *(const float2*)hp;
                acc[0] += v2.x; acc[1] += v2.y;
            } else {
                float4 v4 = *(const float4*)hp;
                acc[0] += v4.x; acc[1] += v4.y; acc[2] += v4.z; acc[3] += v4.w;
            }
        }
    }
    float* ap = g_agg + (size_t)gw*F + lane*V;
    if (V == 1)      ap[0] = acc[0];
    else if (V == 2) *(float2*)ap = make_float2(acc[0], acc[1]);
    else             *(float4*)ap = make_float4(acc[0], acc[1], acc[2], acc[3]);
}

// ---------------- conv0: Fin=4 -> 32 -----------------------------------------
__global__ void k_conv0(const float* __restrict__ wrel,
                        const float* __restrict__ wroot,
                        const float* __restrict__ b){
    __shared__ float wr[128], wt[128], bs[32];
    int t = threadIdx.x;
    if (t < 128){ wr[t] = wrel[t]; wt[t] = wroot[t]; }
    if (t < 32) bs[t] = b[t];
    __syncthreads();
    int i = blockIdx.x*256 + t;
    if (i >= N_NODES) return;
    float4 av = ((const float4*)g_agg)[i];
    float4 hv = ((const float4*)g_h0)[i];
    float a[4] = {av.x,av.y,av.z,av.w};
    float h[4] = {hv.x,hv.y,hv.z,hv.w};
    #pragma unroll
    for (int c=0;c<32;c++){
        float acc = bs[c];
        #pragma unroll
        for (int k=0;k<4;k++) acc += a[k]*wr[k*32+c] + h[k]*wt[k*32+c];
        g_h1[(size_t)i*32 + c] = gelu_f(acc);
    }
}

// ---------------- tiled GEMM w/ packed f32x2 FMA + bias + gelu ----------------
// out = gelu( [agg , h] @ [Wrel ; Wroot] + b );  LAYER 3 fuses parity mean-pool
template<int LAYER>
__global__ void __launch_bounds__(256) k_gemm(const float* __restrict__ Wrel,
                       const float* __restrict__ Wroot,
                       const float* __restrict__ bias){
    constexpr int FIN  = (LAYER==1)?32:(LAYER==2)?64:128;
    constexpr int NOUT = 2*FIN;
    constexpr int KK   = 2*FIN;
    constexpr int BM   = 128;
    constexpr int BN   = (LAYER==1)?64:128;
    constexpr int BK   = 16;
    constexpr int TM   = 8;
    constexpr int TN   = BN/16;         // 4 or 8
    constexpr int TNP  = TN/2;          // packed pairs: 2 or 4
    const float* __restrict__ Aagg = g_agg;
    const float* __restrict__ Ah   = (LAYER==1)?g_h1:(LAYER==2)?g_h2:g_hk;
    float* __restrict__ Out        = (LAYER==1)?g_h2:(LAYER==2)?g_h3:0;
    const int M = (LAYER==3)?KKEEP:N_NODES;

    __shared__ __align__(16) float As[BK][BM];     // transposed A tile
    __shared__ __align__(16) float Bs[BK][BN];

    const int bm = blockIdx.x*BM, bn = blockIdx.y*BN;
    const int tid = threadIdx.x;
    const int tx = tid & 15, ty = tid >> 4;

    const int aRow = tid >> 2;          // 0..63
    const int aCol = (tid & 3) * 4;     // 0,4,8,12
    const int bRow = (BN==128) ? (tid >> 5) : (tid >> 4);
    const int bCol = ((BN==128) ? (tid & 31) : (tid & 15)) * 4;

    unsigned long long accP[TM][TNP];
    #pragma unroll
    for (int i=0;i<TM;i++)
        #pragma unroll
        for (int j=0;j<TNP;j++) accP[i][j]=0ull;

    for (int k0=0;k0<KK;k0+=BK){
        #pragma unroll
        for (int rr=0; rr<BM; rr+=64){
            int row = bm + aRow + rr;
            int k = k0 + aCol;
            float4 v = make_float4(0,0,0,0);
            if (row < M){
                const float* src = (k < FIN) ? (Aagg + (size_t)row*FIN + k)
                                             : (Ah   + (size_t)row*FIN + (k-FIN));
                v = *(const float4*)src;
            }
            As[aCol+0][aRow+rr] = v.x;
            As[aCol+1][aRow+rr] = v.y;
            As[aCol+2][aRow+rr] = v.z;
            As[aCol+3][aRow+rr] = v.w;
        }
        #pragma unroll
        for (int kk2=0; kk2<BK; kk2 += (BN==128?8:16)){
            int k = k0 + bRow + kk2;
            const float* src = (k < FIN) ? (Wrel  + (size_t)k*NOUT + bn + bCol)
                                         : (Wroot + (size_t)(k-FIN)*NOUT + bn + bCol);
            *(float4*)&Bs[bRow+kk2][bCol] = *(const float4*)src;
        }
        __syncthreads();
        #pragma unroll
        for (int kk=0;kk<BK;kk++){
            float a[TM];
            *(float4*)&a[0] = *(const float4*)&As[kk][ty*TM];
            *(float4*)&a[4] = *(const float4*)&As[kk][ty*TM+4];
            unsigned long long bp[TNP];
            #pragma unroll
            for (int j2=0;j2<TNP;j2+=2)
                *(ulonglong2*)&bp[j2] = *(const ulonglong2*)&Bs[kk][tx*TN + 2*j2];
            #pragma unroll
            for (int i=0;i<TM;i++){
                unsigned long long ap = pack2(a[i], a[i]);
                #pragma unroll
                for (int j=0;j<TNP;j++)
                    accP[i][j] = fma2(ap, bp[j], accP[i][j]);
            }
        }
        __syncthreads();
    }

    // unpack
    float acc[TM][TN];
    #pragma unroll
    for (int i=0;i<TM;i++)
        #pragma unroll
        for (int j=0;j<TNP;j++){
            float2 u = unpack2(accP[i][j]);
            acc[i][2*j] = u.x; acc[i][2*j+1] = u.y;
        }

    if (LAYER != 3){
        float bv[TN];
        #pragma unroll
        for (int j=0;j<TN;j++) bv[j] = bias[bn + tx*TN + j];
        #pragma unroll
        for (int i=0;i<TM;i++){
            int row = bm + ty*TM + i;
            if (row < M){
                float o[TN];
                #pragma unroll
                for (int j=0;j<TN;j++) o[j] = gelu_f(acc[i][j] + bv[j]);
                #pragma unroll
                for (int j=0;j<TN;j+=4)
                    *(float4*)(Out + (size_t)row*NOUT + bn + tx*TN + j) = *(float4*)&o[j];
            }
        }
    } else {
        float bv[TN];
        #pragma unroll
        for (int j=0;j<TN;j++) bv[j] = bias[bn + tx*TN + j];
        float p0[TN], p1[TN];
        #pragma unroll
        for (int j=0;j<TN;j++){ p0[j]=0.f; p1[j]=0.f; }
        #pragma unroll
        for (int i=0;i<TM;i++){
            int row = bm + ty*TM + i;          // parity == i&1 (bm, ty*TM even)
            if (row < M){
                #pragma unroll
                for (int j=0;j<TN;j++){
                    float g = gelu_f(acc[i][j] + bv[j]);
                    if (i & 1) p1[j] += g; else p0[j] += g;
                }
            }
        }
        __shared__ float psum[2][16][BN];
        #pragma unroll
        for (int j=0;j<TN;j++){
            psum[0][ty][tx*TN+j] = p0[j];
            psum[1][ty][tx*TN+j] = p1[j];
        }
        __syncthreads();
        int p = tid >> 7, col = tid & 127;     // BN==128 here
        float s = 0.f;
        #pragma unroll
        for (int g=0; g<16; g++) s += psum[p][g][col];
        atomicAdd(&g_gsum[p*256 + bn + col], s);
    }
}

// ---------------- score + sort keys, warp per node ----------------------------
__global__ void k_score(const float* __restrict__ p){
    int gw = (blockIdx.x*blockDim.x + threadIdx.x) >> 5;
    int lane = threadIdx.x & 31;
    if (gw >= N_NODES) return;
    float4 pv = ((const float4*)p)[lane];
    float4 hv = ((const float4*)(g_h3 + (size_t)gw*128))[lane];
    float dot = hv.x*pv.x + hv.y*pv.y + hv.z*pv.z + hv.w*pv.w;
    float pp  = pv.x*pv.x + pv.y*pv.y + pv.z*pv.z + pv.w*pv.w;
    #pragma unroll
    for (int o=16;o;o>>=1){
        dot += __shfl_xor_sync(0xffffffffu, dot, o);
        pp  += __shfl_xor_sync(0xffffffffu, pp,  o);
    }
    if (lane == 0){
        float s = tanhf(dot / sqrtf(pp));
        g_score[gw] = s;
        unsigned u = __float_as_uint(s);
        unsigned asc = (u & 0x80000000u) ? ~u : (u | 0x80000000u);
        g_keysA[gw] = ~asc;              // ascending key = descending score
        g_valsA[gw] = gw;
    }
}

// ---------------- stable radix sort ------------------------------------------
__global__ void k_sorthist(int pass){
    __shared__ int sh[256];
    int t = threadIdx.x;
    if (t < 256) sh[t] = 0;
    __syncthreads();
    int gid = blockIdx.x*1024 + t;
    unsigned key = (pass & 1) ? g_keysB[gid] : g_keysA[gid];
    int d = (key >> (pass*8)) & 255;
    atomicAdd(&sh[d], 1);
    __syncthreads();
    if (t < 256) g_hist[t*NBLK_SORT + blockIdx.x] = sh[t];
}

__global__ void k_sortscatter(int pass){
    __shared__ int wc[32*256];
    int t = threadIdx.x;
    int w = t >> 5, lane = t & 31;
    for (int i=t;i<32*256;i+=1024) wc[i] = 0;
    __syncthreads();
    int gid = blockIdx.x*1024 + t;
    unsigned key; int val;
    if (pass & 1){ key = g_keysB[gid]; val = g_valsB[gid]; }
    else         { key = g_keysA[gid]; val = g_valsA[gid]; }
    int d = (key >> (pass*8)) & 255;
    unsigned m = __match_any_sync(0xffffffffu, d);
    int lr = __popc(m & ((1u << lane) - 1u));
    int leader = __ffs(m) - 1;
    if (lane == leader) wc[w*256 + d] = __popc(m);
    __syncthreads();
    if (t < 256){
        int run = 0;
        #pragma unroll
        for (int ww=0; ww<32; ww++){
            int tmp = wc[ww*256 + t];
            wc[ww*256 + t] = run;
            run += tmp;
        }
    }
    __syncthreads();
    int pos = g_offs[d*NBLK_SORT + blockIdx.x] + wc[w*256 + d] + lr;
    if (pass & 1){ g_keysA[pos] = key; g_valsA[pos] = val; }
    else         { g_keysB[pos] = key; g_valsB[pos] = val; }
}

// ---------------- gather kept nodes -------------------------------------------
__global__ void k_hk(){
    int r = (blockIdx.x*blockDim.x + threadIdx.x) >> 5;
    int lane = threadIdx.x & 31;
    if (r >= KKEEP) return;
    int orig = g_valsA[r];
    float v = g_score[orig];
    float4 hv = ((const float4*)(g_h3 + (size_t)orig*128))[lane];
    hv.x *= v; hv.y *= v; hv.z *= v; hv.w *= v;
    ((float4*)(g_hk + (size_t)r*128))[lane] = hv;
    if (lane == 0) g_newid[orig] = r;
}

// ---------------- filtered CSR over kept nodes -------------------------------
__global__ void k_deg2(const int* __restrict__ ei){
    int e = blockIdx.x*blockDim.x + threadIdx.x;
    if (e >= N_EDGES) return;
    int s2 = g_newid[ei[e]];
    int d2 = g_newid[ei[N_EDGES + e]];
    if (s2 >= 0 && d2 >= 0) atomicAdd(&g_cur2[d2], 1);
}
__global__ void k_scatter2(const int* __restrict__ ei){
    int e = blockIdx.x*blockDim.x + threadIdx.x;
    if (e >= N_EDGES) return;
    int s2 = g_newid[ei[e]];
    int d2 = g_newid[ei[N_EDGES + e]];
    if (s2 >= 0 && d2 >= 0){
        int p = atomicAdd(&g_cur2[d2], 1);
        g_csr2[p] = s2;
    }
}

// ---------------- final projection --------------------------------------------
__global__ void k_final(const float* __restrict__ w_out,
                        const float* __restrict__ b_out,
                        float* __restrict__ out){
    __shared__ float red[256];
    int t = threadIdx.x;
    const float inv = 1.0f/15000.0f;
    float acc = g_gsum[t]*inv*w_out[t] + g_gsum[256+t]*inv*w_out[256+t];
    red[t] = acc;
    __syncthreads();
    for (int s=128; s; s>>=1){
        if (t < s) red[t] += red[t+s];
        __syncthreads();
    }
    if (t == 0) out[0] = red[0] + b_out[0];
}

// ---------------- scan helper --------------------------------------------------
static inline void run_scan(int mode){
    int n = (mode==0)?N_NODES:(mode==1)?KKEEP:HISTN;
    int nb = (n + SCAN_TILE - 1)/SCAN_TILE;
    k_scanA<<<nb,256>>>(mode);
    k_scanB<<<1,32>>>(mode);
    k_scanC<<<nb,256>>>(mode);
}

// ---------------- launch sequence ----------------------------------------------
extern "C" void kernel_launch(void* const* d_in, const int* in_sizes, int n_in,
                              void* d_out, int out_size){
    const float* x       = (const float*)d_in[0];
    const int*   ei      = (const int*)  d_in[1];
    const float* wd_root = (const float*)d_in[2];
    const float* wd_b    = (const float*)d_in[3];
    const float* w0_rel  = (const float*)d_in[4];
    const float* w0_root = (const float*)d_in[5];
    const float* w0_b    = (const float*)d_in[6];
    const float* w1_rel  = (const float*)d_in[7];
    const float* w1_root = (const float*)d_in[8];
    const float* w1_b    = (const float*)d_in[9];
    const float* w2_rel  = (const float*)d_in[10];
    const float* w2_root = (const float*)d_in[11];
    const float* w2_b    = (const float*)d_in[12];
    const float* pool_p  = (const float*)d_in[13];
    const float* w3_rel  = (const float*)d_in[14];
    const float* w3_root = (const float*)d_in[15];
    const float* w3_b    = (const float*)d_in[16];
    const float* w_out   = (const float*)d_in[17];
    const float* b_out   = (const float*)d_in[18];
    float* out = (float*)d_out;

    const int GN256   = (N_NODES + 255)/256;          // 196 (== NPAD/256)
    const int GE256   = (N_EDGES + 255)/256;
    const int GWARP_N = (N_NODES*32 + 255)/256;
    const int GWARP_K = (KKEEP*32 + 255)/256;

    k_init<<<GN256,256>>>();
    k_dense<<<GN256,256>>>(x, wd_root, wd_b);

    // CSR (by dst), reused for convs 0-2
    k_deg<<<GE256,256>>>(ei);
    run_scan(0);
    k_scatter<<<GE256,256>>>(ei);

    // conv0: 4 -> 32
    k_agg4<<<GWARP_N,256>>>();
    k_conv0<<<GN256,256>>>(w0_rel, w0_root, w0_b);

    // conv1: 32 -> 64
    k_agg<1><<<GWARP_N,256>>>();
    k_gemm<1><<<dim3((N_NODES+127)/128, 1),256>>>(w1_rel, w1_root, w1_b);

    // conv2: 64 -> 128
    k_agg<2><<<GWARP_N,256>>>();
    k_gemm<2><<<dim3((N_NODES+127)/128, 1),256>>>(w2_rel, w2_root, w2_b);

    // topk: scores(+keys) + stable radix sort
    k_score<<<GWARP_N,256>>>(pool_p);
    for (int pass=0; pass<4; pass++){
        k_sorthist<<<NBLK_SORT,1024>>>(pass);
        run_scan(2);
        k_sortscatter<<<NBLK_SORT,1024>>>(pass);
    }
    k_hk<<<GWARP_K,256>>>();

    // filtered CSR + conv3: 128 -> 256 (pooling fused into epilogue)
    k_deg2<<<GE256,256>>>(ei);
    run_scan(1);
    k_scatter2<<<GE256,256>>>(ei);
    k_agg<3><<<GWARP_K,256>>>();
    k_gemm<3><<<dim3((KKEEP+127)/128, 2),256>>>(w3_rel, w3_root, w3_b);

    k_final<<<1,256>>>(w_out, b_out, out);
}

// round 17
// speedup vs baseline: 1.0469x; 1.0355x over previous
#include <cuda_runtime.h>
#include <math.h>

#define N_NODES 50000
#define N_EDGES 1600000
#define KKEEP   30000
#define NPAD    50176          // 49 * 1024 == 196*256 (k_init grid covers it exactly)
#define NBLK_SORT 49
#define HISTN   (256*NBLK_SORT)
#define SCAN_TILE 4096

// ---------------- static device scratch (no allocation allowed) -------------
__device__ __align__(128) float g_h0[N_NODES*4];
__device__ __align__(128) float g_h1[N_NODES*32];
__device__ __align__(128) float g_h2[N_NODES*64];
__device__ __align__(128) float g_h3[N_NODES*128];
__device__ __align__(128) float g_agg[N_NODES*128];
__device__ __align__(128) float g_hk[KKEEP*128];
__device__ float g_score[N_NODES];

__device__ int g_off[N_NODES+1];
__device__ int g_cur[N_NODES];
__device__ int g_csr[N_EDGES];
__device__ int g_off2[KKEEP+1];
__device__ int g_cur2[KKEEP];
__device__ int g_csr2[N_EDGES];

__device__ unsigned g_keysA[NPAD], g_keysB[NPAD];
__device__ int      g_valsA[NPAD], g_valsB[NPAD];
__device__ int      g_hist[HISTN];
__device__ int      g_newid[N_NODES];
__device__ float    g_gsum[512];
__device__ int      g_bsum[64];
__device__ int      g_barc, g_barp;

__device__ __forceinline__ float gelu_f(float v){
    return 0.5f*v*(1.0f + erff(v*0.70710678118654752440f));
}

// ---------------- packed f32x2 helpers (Blackwell FFMA2) ---------------------
__device__ __forceinline__ unsigned long long pack2(float x, float y){
    unsigned long long r;
    asm("mov.b64 %0, {%1, %2};" : "=l"(r) : "f"(x), "f"(y));
    return r;
}
__device__ __forceinline__ unsigned long long fma2(unsigned long long a,
                                                   unsigned long long b,
                                                   unsigned long long c){
    unsigned long long d;
    asm("fma.rn.f32x2 %0, %1, %2, %3;" : "=l"(d) : "l"(a), "l"(b), "l"(c));
    return d;
}
__device__ __forceinline__ float2 unpack2(unsigned long long v){
    float lo, hi;
    asm("mov.b64 {%0, %1}, %2;" : "=f"(lo), "=f"(hi) : "l"(v));
    return make_float2(lo, hi);
}

// ---------------- grid barrier for the persistent sort kernel ----------------
__device__ __forceinline__ void gridbar(int nb, int target){
    __threadfence();
    __syncthreads();
    if (threadIdx.x == 0){
        int t = atomicAdd(&g_barc, 1);
        if (t == nb-1){
            atomicExch(&g_barc, 0);
            __threadfence();
            atomicExch(&g_barp, target);
        } else {
            while (atomicAdd(&g_barp, 0) < target) { __nanosleep(64); }
        }
    }
    __syncthreads();
}

// ---------------- init: zero counters, newid=-1, pad sort keys ---------------
__global__ void k_init(){
    int i = blockIdx.x*blockDim.x + threadIdx.x;
    if (i == 0){ g_barc = 0; g_barp = 0; }
    if (i < N_NODES){ g_cur[i] = 0; g_newid[i] = -1; }
    else if (i < NPAD){ g_keysA[i] = 0xFFFFFFFFu; g_valsA[i] = -1; }
    if (i < KKEEP)  g_cur2[i] = 0;
    if (i < 512)    g_gsum[i] = 0.f;
}

// ---------------- dense input layer: h0 = gelu(x @ wd_root + b) -------------
__global__ void k_dense(const float* __restrict__ x,
                        const float* __restrict__ w,
                        const float* __restrict__ b){
    __shared__ float ws[256];
    __shared__ float bs[4];
    int t = threadIdx.x;
    if (t < 256) ws[t] = w[t];
    if (t < 4)   bs[t] = b[t];
    __syncthreads();
    int i = blockIdx.x*256 + t;
    if (i >= N_NODES) return;
    float a0=bs[0], a1=bs[1], a2=bs[2], a3=bs[3];
    const float4* x4 = (const float4*)(x + (size_t)i*64);
    #pragma unroll
    for (int q=0;q<16;q++){
        float4 xv = x4[q];
        const float* wp = ws + q*16;
        a0 += xv.x*wp[0] + xv.y*wp[4] + xv.z*wp[8]  + xv.w*wp[12];
        a1 += xv.x*wp[1] + xv.y*wp[5] + xv.z*wp[9]  + xv.w*wp[13];
        a2 += xv.x*wp[2] + xv.y*wp[6] + xv.z*wp[10] + xv.w*wp[14];
        a3 += xv.x*wp[3] + xv.y*wp[7] + xv.z*wp[11] + xv.w*wp[15];
    }
    ((float4*)g_h0)[i] = make_float4(gelu_f(a0),gelu_f(a1),gelu_f(a2),gelu_f(a3));
}

// ---------------- CSR build --------------------------------------------------
__global__ void k_deg(const int* __restrict__ ei){
    int e = blockIdx.x*blockDim.x + threadIdx.x;
    if (e < N_EDGES) atomicAdd(&g_cur[ei[N_EDGES + e]], 1);
}
__global__ void k_scatter(const int* __restrict__ ei){
    int e = blockIdx.x*blockDim.x + threadIdx.x;
    if (e < N_EDGES){
        int d = ei[N_EDGES + e];
        int p = atomicAdd(&g_cur[d], 1);
        g_csr[p] = ei[e];
    }
}

// ---------------- multi-block exclusive scan (3 phases) ----------------------
__device__ __forceinline__ void scan_src(int mode, const int*& in, int& n){
    if (mode==0){ in=g_cur;  n=N_NODES; }
    else { in=g_cur2; n=KKEEP; }
}

__global__ void k_scanA(int mode){
    const int* in; int n;
    scan_src(mode, in, n);
    int t = threadIdx.x;
    int base = blockIdx.x*SCAN_TILE + t*16;
    int s = 0;
    #pragma unroll
    for (int j=0;j<16;j++){ int i = base+j; if (i < n) s += in[i]; }
    __shared__ int red[256];
    red[t] = s;
    __syncthreads();
    #pragma unroll
    for (int st=128; st; st>>=1){
        if (t < st) red[t] += red[t+st];
        __syncthreads();
    }
    if (t == 0) g_bsum[blockIdx.x] = red[0];
}

__global__ void k_scanB(int mode){
    int n = (mode==0)?N_NODES:KKEEP;
    int nb = (n + SCAN_TILE - 1)/SCAN_TILE;
    int t = threadIdx.x;
    int v = (t < nb) ? g_bsum[t] : 0;
    int incl = v;
    #pragma unroll
    for (int o=1;o<32;o<<=1){
        int u = __shfl_up_sync(0xffffffffu, incl, o);
        if (t >= o) incl += u;
    }
    if (t < nb) g_bsum[t] = incl - v;
    if (t == nb-1){
        if (mode==0) g_off[N_NODES] = incl;
        else g_off2[KKEEP] = incl;
    }
}

__global__ void k_scanC(int mode){
    const int* in; int* out; int* cpy; int n;
    if (mode==0){ in=g_cur;  out=g_off;  cpy=g_cur;  n=N_NODES; }
    else { in=g_cur2; out=g_off2; cpy=g_cur2; n=KKEEP; }
    int t = threadIdx.x;
    int base = blockIdx.x*SCAN_TILE + t*16;
    int vals[16]; int s = 0;
    #pragma unroll
    for (int j=0;j<16;j++){
        int i = base+j;
        vals[j] = (i < n) ? in[i] : 0;
        s += vals[j];
    }
    __shared__ int sh[256];
    sh[t] = s;
    __syncthreads();
    #pragma unroll
    for (int d=1; d<256; d<<=1){
        int v = 0;
        if (t >= d) v = sh[t-d];
        __syncthreads();
        if (t >= d) sh[t] += v;
        __syncthreads();
    }
    int run = g_bsum[blockIdx.x] + sh[t] - s;
    #pragma unroll
    for (int j=0;j<16;j++){
        int i = base+j;
        if (i < n){
            out[i] = run;
            if (cpy) cpy[i] = run;
            run += vals[j];
        }
    }
}

// ---------------- aggregation, F=4 -------------------------------------------
__global__ void k_agg4(){
    int gw = (blockIdx.x*blockDim.x + threadIdx.x) >> 5;
    int lane = threadIdx.x & 31;
    if (gw >= N_NODES) return;
    int s0 = g_off[gw], s1 = g_off[gw+1];
    float4 acc = make_float4(0,0,0,0);
    for (int e = s0 + lane; e < s1; e += 32){
        int s = g_csr[e];
        float4 v = *(const float4*)(g_h0 + (size_t)s*4);
        acc.x += v.x; acc.y += v.y; acc.z += v.z; acc.w += v.w;
    }
    #pragma unroll
    for (int o=16;o;o>>=1){
        acc.x += __shfl_down_sync(0xffffffffu, acc.x, o);
        acc.y += __shfl_down_sync(0xffffffffu, acc.y, o);
        acc.z += __shfl_down_sync(0xffffffffu, acc.z, o);
        acc.w += __shfl_down_sync(0xffffffffu, acc.w, o);
    }
    if (lane == 0) *(float4*)(g_agg + (size_t)gw*4) = acc;
}

// ---------------- aggregation, F in {32,64,128} (warp per node) --------------
template<int LAYER>
__global__ void k_agg(){
    constexpr int F = (LAYER==1)?32:(LAYER==2)?64:128;
    constexpr int V = F/32;
    const float* __restrict__ hin = (LAYER==1)?g_h1:(LAYER==2)?g_h2:g_hk;
    const int* __restrict__ off   = (LAYER==3)?g_off2:g_off;
    const int* __restrict__ csr   = (LAYER==3)?g_csr2:g_csr;
    const int n = (LAYER==3)?KKEEP:N_NODES;

    int gw = (blockIdx.x*blockDim.x + threadIdx.x) >> 5;
    int lane = threadIdx.x & 31;
    if (gw >= n) return;
    float acc[V];
    #pragma unroll
    for (int v=0;v<V;v++) acc[v]=0.f;
    int s1 = off[gw+1];
    for (int base = off[gw]; base < s1; base += 32){
        int idx = base + lane;
        int s = (idx < s1) ? csr[idx] : 0;
        int cnt = s1 - base; if (cnt > 32) cnt = 32;
        for (int j=0;j<cnt;j++){
            int sj = __shfl_sync(0xffffffffu, s, j);
            const float* hp = hin + (size_t)sj*F + lane*V;
            if (V == 1){
                acc[0] += hp[0];
            } else if (V == 2){
                float2 v2 = *(const float2*)hp;
                acc[0] += v2.x; acc[1] += v2.y;
            } else {
                float4 v4 = *(const float4*)hp;
                acc[0] += v4.x; acc[1] += v4.y; acc[2] += v4.z; acc[3] += v4.w;
            }
        }
    }
    float* ap = g_agg + (size_t)gw*F + lane*V;
    if (V == 1)      ap[0] = acc[0];
    else if (V == 2) *(float2*)ap = make_float2(acc[0], acc[1]);
    else             *(float4*)ap = make_float4(acc[0], acc[1], acc[2], acc[3]);
}

// ---------------- conv0: Fin=4 -> 32 -----------------------------------------
__global__ void k_conv0(const float* __restrict__ wrel,
                        const float* __restrict__ wroot,
                        const float* __restrict__ b){
    __shared__ float wr[128], wt[128], bs[32];
    int t = threadIdx.x;
    if (t < 128){ wr[t] = wrel[t]; wt[t] = wroot[t]; }
    if (t < 32) bs[t] = b[t];
    __syncthreads();
    int i = blockIdx.x*256 + t;
    if (i >= N_NODES) return;
    float4 av = ((const float4*)g_agg)[i];
    float4 hv = ((const float4*)g_h0)[i];
    float a[4] = {av.x,av.y,av.z,av.w};
    float h[4] = {hv.x,hv.y,hv.z,hv.w};
    #pragma unroll
    for (int c=0;c<32;c++){
        float acc = bs[c];
        #pragma unroll
        for (int k=0;k<4;k++) acc += a[k]*wr[k*32+c] + h[k]*wt[k*32+c];
        g_h1[(size_t)i*32 + c] = gelu_f(acc);
    }
}

// ---------------- tiled GEMM w/ packed f32x2 FMA + bias + gelu ----------------
// LAYER 2 fuses score + sort-key generation; LAYER 3 fuses parity mean-pool
template<int LAYER>
__global__ void __launch_bounds__(256) k_gemm(const float* __restrict__ Wrel,
                       const float* __restrict__ Wroot,
                       const float* __restrict__ bias,
                       const float* __restrict__ Pool){
    constexpr int FIN  = (LAYER==1)?32:(LAYER==2)?64:128;
    constexpr int NOUT = 2*FIN;
    constexpr int KK   = 2*FIN;
    constexpr int BM   = 128;
    constexpr int BN   = (LAYER==1)?64:128;
    constexpr int BK   = 16;
    constexpr int TM   = 8;
    constexpr int TN   = BN/16;         // 4 or 8
    constexpr int TNP  = TN/2;          // packed pairs: 2 or 4
    const float* __restrict__ Aagg = g_agg;
    const float* __restrict__ Ah   = (LAYER==1)?g_h1:(LAYER==2)?g_h2:g_hk;
    float* __restrict__ Out        = (LAYER==1)?g_h2:(LAYER==2)?g_h3:0;
    const int M = (LAYER==3)?KKEEP:N_NODES;

    __shared__ __align__(16) float As[BK][BM];     // transposed A tile
    __shared__ __align__(16) float Bs[BK][BN];

    const int bm = blockIdx.x*BM, bn = blockIdx.y*BN;
    const int tid = threadIdx.x;
    const int tx = tid & 15, ty = tid >> 4;

    const int aRow = tid >> 2;          // 0..63
    const int aCol = (tid & 3) * 4;     // 0,4,8,12
    const int bRow = (BN==128) ? (tid >> 5) : (tid >> 4);
    const int bCol = ((BN==128) ? (tid & 31) : (tid & 15)) * 4;

    unsigned long long accP[TM][TNP];
    #pragma unroll
    for (int i=0;i<TM;i++)
        #pragma unroll
        for (int j=0;j<TNP;j++) accP[i][j]=0ull;

    for (int k0=0;k0<KK;k0+=BK){
        #pragma unroll
        for (int rr=0; rr<BM; rr+=64){
            int row = bm + aRow + rr;
            int k = k0 + aCol;
            float4 v = make_float4(0,0,0,0);
            if (row < M){
                const float* src = (k < FIN) ? (Aagg + (size_t)row*FIN + k)
                                             : (Ah   + (size_t)row*FIN + (k-FIN));
                v = *(const float4*)src;
            }
            As[aCol+0][aRow+rr] = v.x;
            As[aCol+1][aRow+rr] = v.y;
            As[aCol+2][aRow+rr] = v.z;
            As[aCol+3][aRow+rr] = v.w;
        }
        #pragma unroll
        for (int kk2=0; kk2<BK; kk2 += (BN==128?8:16)){
            int k = k0 + bRow + kk2;
            const float* src = (k < FIN) ? (Wrel  + (size_t)k*NOUT + bn + bCol)
                                         : (Wroot + (size_t)(k-FIN)*NOUT + bn + bCol);
            *(float4*)&Bs[bRow+kk2][bCol] = *(const float4*)src;
        }
        __syncthreads();
        #pragma unroll
        for (int kk=0;kk<BK;kk++){
            float a[TM];
            *(float4*)&a[0] = *(const float4*)&As[kk][ty*TM];
            *(float4*)&a[4] = *(const float4*)&As[kk][ty*TM+4];
            unsigned long long bp[TNP];
            #pragma unroll
            for (int j2=0;j2<TNP;j2+=2)
                *(ulonglong2*)&bp[j2] = *(const ulonglong2*)&Bs[kk][tx*TN + 2*j2];
            #pragma unroll
            for (int i=0;i<TM;i++){
                unsigned long long ap = pack2(a[i], a[i]);
                #pragma unroll
                for (int j=0;j<TNP;j++)
                    accP[i][j] = fma2(ap, bp[j], accP[i][j]);
            }
        }
        __syncthreads();
    }

    // unpack
    float acc[TM][TN];
    #pragma unroll
    for (int i=0;i<TM;i++)
        #pragma unroll
        for (int j=0;j<TNP;j++){
            float2 u = unpack2(accP[i][j]);
            acc[i][2*j] = u.x; acc[i][2*j+1] = u.y;
        }

    if (LAYER == 1){
        float bv[TN];
        #pragma unroll
        for (int j=0;j<TN;j++) bv[j] = bias[bn + tx*TN + j];
        #pragma unroll
        for (int i=0;i<TM;i++){
            int row = bm + ty*TM + i;
            if (row < M){
                float o[TN];
                #pragma unroll
                for (int j=0;j<TN;j++) o[j] = gelu_f(acc[i][j] + bv[j]);
                #pragma unroll
                for (int j=0;j<TN;j+=4)
                    *(float4*)(Out + (size_t)row*NOUT + bn + tx*TN + j) = *(float4*)&o[j];
            }
        }
    } else if (LAYER == 2){
        // store h3 + fused score/sort-key generation (BN==NOUT==128, bn==0)
        float bv[TN], pv[TN];
        #pragma unroll
        for (int j=0;j<TN;j++){ bv[j] = bias[tx*TN + j]; pv[j] = Pool[tx*TN + j]; }
        float ppart = 0.f;
        #pragma unroll
        for (int j=0;j<TN;j++) ppart += pv[j]*pv[j];
        #pragma unroll
        for (int o2=8;o2;o2>>=1) ppart += __shfl_xor_sync(0xffffffffu, ppart, o2, 16);
        float norm = sqrtf(ppart);
        #pragma unroll
        for (int i=0;i<TM;i++){
            int row = bm + ty*TM + i;
            if (row < M){                          // uniform across the 16-lane tx group
                float o[TN];
                float dot = 0.f;
                #pragma unroll
                for (int j=0;j<TN;j++){
                    o[j] = gelu_f(acc[i][j] + bv[j]);
                    dot += o[j]*pv[j];
                }
                #pragma unroll
                for (int j=0;j<TN;j+=4)
                    *(float4*)(Out + (size_t)row*NOUT + tx*TN + j) = *(float4*)&o[j];
                #pragma unroll
                for (int o2=8;o2;o2>>=1) dot += __shfl_xor_sync(0xffffffffu, dot, o2, 16);
                if (tx == 0){
                    float s = tanhf(dot / norm);
                    g_score[row] = s;
                    unsigned u = __float_as_uint(s);
                    unsigned asc = (u & 0x80000000u) ? ~u : (u | 0x80000000u);
                    g_keysA[row] = ~asc;           // ascending key = descending score
                    g_valsA[row] = row;
                }
            }
        }
    } else {
        // fused parity mean-pool
        float bv[TN];
        #pragma unroll
        for (int j=0;j<TN;j++) bv[j] = bias[bn + tx*TN + j];
        float p0[TN], p1[TN];
        #pragma unroll
        for (int j=0;j<TN;j++){ p0[j]=0.f; p1[j]=0.f; }
        #pragma unroll
        for (int i=0;i<TM;i++){
            int row = bm + ty*TM + i;          // parity == i&1 (bm, ty*TM even)
            if (row < M){
                #pragma unroll
                for (int j=0;j<TN;j++){
                    float g = gelu_f(acc[i][j] + bv[j]);
                    if (i & 1) p1[j] += g; else p0[j] += g;
                }
            }
        }
        __shared__ float psum[2][16][BN];
        #pragma unroll
        for (int j=0;j<TN;j++){
            psum[0][ty][tx*TN+j] = p0[j];
            psum[1][ty][tx*TN+j] = p1[j];
        }
        __syncthreads();
        int p = tid >> 7, col = tid & 127;     // BN==128 here
        float s = 0.f;
        #pragma unroll
        for (int g=0; g<16; g++) s += psum[p][g][col];
        atomicAdd(&g_gsum[p*256 + bn + col], s);
    }
}

// ---------------- fused 4-pass stable radix sort + hk gather ------------------
// 49 persistent blocks x 1024 threads (co-resident: 49 << 148 SMs)
__global__ void __launch_bounds__(1024) k_sortall(){
    __shared__ int wc[32*256];
    __shared__ int s_tot[256];
    __shared__ int s_off[256];
    const int t = threadIdx.x, b = blockIdx.x;
    const int w = t >> 5, lane = t & 31;
    int bar = 0;

    #pragma unroll 1
    for (int pass=0; pass<4; pass++){
        const unsigned* __restrict__ keys = (pass&1) ? g_keysB : g_keysA;
        const int*      __restrict__ vals = (pass&1) ? g_valsB : g_valsA;
        unsigned* __restrict__ okeys = (pass&1) ? g_keysA : g_keysB;
        int*      __restrict__ ovals = (pass&1) ? g_valsA : g_valsB;

        // block-local histogram
        if (t < 256) s_tot[t] = 0;
        __syncthreads();
        int gid = b*1024 + t;
        unsigned key = keys[gid];
        int val = vals[gid];
        int d = (key >> (pass*8)) & 255;
        atomicAdd(&s_tot[d], 1);
        __syncthreads();
        if (t < 256) g_hist[t*NBLK_SORT + b] = s_tot[t];
        gridbar(NBLK_SORT, ++bar);

        // each block derives its own scatter offsets from the global hist
        if (t < 256){
            int part = 0, tot = 0;
            #pragma unroll 7
            for (int bb=0; bb<NBLK_SORT; bb++){
                int c = g_hist[t*NBLK_SORT + bb];
                if (bb < b) part += c;
                tot += c;
            }
            s_tot[t] = tot;
            s_off[t] = part;
        }
        __syncthreads();
        // inclusive Hillis-Steele scan of digit totals (reuse wc as temp)
        if (t < 256) wc[t] = s_tot[t];
        __syncthreads();
        for (int dd=1; dd<256; dd<<=1){
            int v2 = 0;
            if (t < 256 && t >= dd) v2 = wc[t-dd];
            __syncthreads();
            if (t < 256 && t >= dd) wc[t] += v2;
            __syncthreads();
        }
        if (t < 256) s_off[t] += (t==0 ? 0 : wc[t-1]);
        __syncthreads();

        // stable intra-block ranking + scatter
        for (int i=t;i<32*256;i+=1024) wc[i] = 0;
        __syncthreads();
        unsigned m = __match_any_sync(0xffffffffu, d);
        int lr = __popc(m & ((1u << lane) - 1u));
        int leader = __ffs(m) - 1;
        if (lane == leader) wc[w*256 + d] = __popc(m);
        __syncthreads();
        if (t < 256){
            int run = 0;
            #pragma unroll
            for (int ww=0; ww<32; ww++){
                int tmp = wc[ww*256 + t];
                wc[ww*256 + t] = run;
                run += tmp;
            }
        }
        __syncthreads();
        int pos = s_off[d] + wc[w*256 + d] + lr;
        okeys[pos] = key;
        ovals[pos] = val;
        gridbar(NBLK_SORT, ++bar);
    }

    // fused hk gather: hk[r] = h3[perm[r]] * score[perm[r]] ; result is in A
    const int nw = NBLK_SORT*32;
    for (int r = b*32 + w; r < KKEEP; r += nw){
        int orig = g_valsA[r];
        float v = g_score[orig];
        float4 hv = ((const float4*)(g_h3 + (size_t)orig*128))[lane];
        hv.x *= v; hv.y *= v; hv.z *= v; hv.w *= v;
        ((float4*)(g_hk + (size_t)r*128))[lane] = hv;
        if (lane == 0) g_newid[orig] = r;
    }
}

// ---------------- filtered CSR over kept nodes -------------------------------
__global__ void k_deg2(const int* __restrict__ ei){
    int e = blockIdx.x*blockDim.x + threadIdx.x;
    if (e >= N_EDGES) return;
    int s2 = g_newid[ei[e]];
    int d2 = g_newid[ei[N_EDGES + e]];
    if (s2 >= 0 && d2 >= 0) atomicAdd(&g_cur2[d2], 1);
}
__global__ void k_scatter2(const int* __restrict__ ei){
    int e = blockIdx.x*blockDim.x + threadIdx.x;
    if (e >= N_EDGES) return;
    int s2 = g_newid[ei[e]];
    int d2 = g_newid[ei[N_EDGES + e]];
    if (s2 >= 0 && d2 >= 0){
        int p = atomicAdd(&g_cur2[d2], 1);
        g_csr2[p] = s2;
    }
}

// ---------------- final projection --------------------------------------------
__global__ void k_final(const float* __restrict__ w_out,
                        const float* __restrict__ b_out,
                        float* __restrict__ out){
    __shared__ float red[256];
    int t = threadIdx.x;
    const float inv = 1.0f/15000.0f;
    float acc = g_gsum[t]*inv*w_out[t] + g_gsum[256+t]*inv*w_out[256+t];
    red[t] = acc;
    __syncthreads();
    for (int s=128; s; s>>=1){
        if (t < s) red[t] += red[t+s];
        __syncthreads();
    }
    if (t == 0) out[0] = red[0] + b_out[0];
}

// ---------------- scan helper --------------------------------------------------
static inline void run_scan(int mode){
    int n = (mode==0)?N_NODES:KKEEP;
    int nb = (n + SCAN_TILE - 1)/SCAN_TILE;
    k_scanA<<<nb,256>>>(mode);
    k_scanB<<<1,32>>>(mode);
    k_scanC<<<nb,256>>>(mode);
}

// ---------------- launch sequence ----------------------------------------------
extern "C" void kernel_launch(void* const* d_in, const int* in_sizes, int n_in,
                              void* d_out, int out_size){
    const float* x       = (const float*)d_in[0];
    const int*   ei      = (const int*)  d_in[1];
    const float* wd_root = (const float*)d_in[2];
    const float* wd_b    = (const float*)d_in[3];
    const float* w0_rel  = (const float*)d_in[4];
    const float* w0_root = (const float*)d_in[5];
    const float* w0_b    = (const float*)d_in[6];
    const float* w1_rel  = (const float*)d_in[7];
    const float* w1_root = (const float*)d_in[8];
    const float* w1_b    = (const float*)d_in[9];
    const float* w2_rel  = (const float*)d_in[10];
    const float* w2_root = (const float*)d_in[11];
    const float* w2_b    = (const float*)d_in[12];
    const float* pool_p  = (const float*)d_in[13];
    const float* w3_rel  = (const float*)d_in[14];
    const float* w3_root = (const float*)d_in[15];
    const float* w3_b    = (const float*)d_in[16];
    const float* w_out   = (const float*)d_in[17];
    const float* b_out   = (const float*)d_in[18];
    float* out = (float*)d_out;

    const int GN256   = (N_NODES + 255)/256;          // 196 (== NPAD/256)
    const int GE256   = (N_EDGES + 255)/256;
    const int GWARP_N = (N_NODES*32 + 255)/256;
    const int GWARP_K = (KKEEP*32 + 255)/256;

    k_init<<<GN256,256>>>();
    k_dense<<<GN256,256>>>(x, wd_root, wd_b);

    // CSR (by dst), reused for convs 0-2
    k_deg<<<GE256,256>>>(ei);
    run_scan(0);
    k_scatter<<<GE256,256>>>(ei);

    // conv0: 4 -> 32
    k_agg4<<<GWARP_N,256>>>();
    k_conv0<<<GN256,256>>>(w0_rel, w0_root, w0_b);

    // conv1: 32 -> 64
    k_agg<1><<<GWARP_N,256>>>();
    k_gemm<1><<<dim3((N_NODES+127)/128, 1),256>>>(w1_rel, w1_root, w1_b, 0);

    // conv2: 64 -> 128 (+ fused score & sort keys)
    k_agg<2><<<GWARP_N,256>>>();
    k_gemm<2><<<dim3((N_NODES+127)/128, 1),256>>>(w2_rel, w2_root, w2_b, pool_p);

    // topk: fused 4-pass stable radix sort + hk gather (1 persistent kernel)
    k_sortall<<<NBLK_SORT,1024>>>();

    // filtered CSR + conv3: 128 -> 256 (pooling fused into epilogue)
    k_deg2<<<GE256,256>>>(ei);
    run_scan(1);
    k_scatter2<<<GE256,256>>>(ei);
    k_agg<3><<<GWARP_K,256>>>();
    k_gemm<3><<<dim3((KKEEP+127)/128, 2),256>>>(w3_rel, w3_root, w3_b, 0);

    k_final<<<1,256>>>(w_out, b_out, out);
}